// round 4
// baseline (speedup 1.0000x reference)
#include <cuda_runtime.h>
#include <cuda_bf16.h>
#include <cstdint>
#include <cstddef>

#define NE   32
#define NK   4
#define NH   2048
#define NI   2048
#define NT   512
#define NCAP 256
#define N1   4096   // 2*I

// ---------------- scratch (static device globals; no runtime allocation) ----------------
__device__ int8_t g_qx[NT * NH];                       // 1 MB
__device__ float  g_xscale[NT];
__device__ int    g_topk_ids[NT * NK];
__device__ float  g_topk_w[NT * NK];
__device__ int    g_pos[NT * NK];
__device__ int    g_count[NE];
__device__ int    g_row_tok[NE * NCAP];
__device__ int    g_row_flat[NE * NCAP];
__device__ float  g_act[(size_t)NE * NCAP * NI];       // 64 MB
__device__ int8_t g_q2[(size_t)NE * NCAP * NI];        // 16 MB
__device__ float  g_s2[NE * NCAP];
__device__ float  g_dn[(size_t)NT * NK * NH];          // 16 MB

// weight-encoding handling
__device__ int    g_mode;                              // 0=int8 packed, 1=int32, 2=f32, 3=bf16
__device__ int    g_gu_swap;                           // 1 if (sb_a,sb_b) = (bias,scale)
__device__ int    g_dn_swap;
__device__ int8_t g_wp1[(size_t)NE * NH * N1];         // 256 MB repacked gate_up
__device__ int8_t g_wp2[(size_t)NE * NI * NH];         // 128 MB repacked down

// ---------------- 0a. detect weight dtype encoding ----------------
__global__ void detect_dtype(const void* __restrict__ w) {
    __shared__ int votes[4];
    if (threadIdx.x < 4) votes[threadIdx.x] = 0;
    __syncthreads();
    const int* wi = (const int*)w;
    int v8 = 0, v32 = 0, vf = 0, vb = 0;
    for (int i = threadIdx.x; i < 8192; i += 256) {
        int v = wi[i];
        if (v == 0) continue;
        if (v >= -127 && v <= 127) { v32++; continue; }                  // int32 element
        float f = __int_as_float(v);
        if (fabsf(f) <= 127.f && f == rintf(f)) { vf++; continue; }      // f32 integer value
        float b0 = __uint_as_float(((unsigned)v & 0xFFFFu) << 16);       // bf16 pair
        float b1 = __uint_as_float(((unsigned)v) & 0xFFFF0000u);
        if (fabsf(b0) <= 127.f && b0 == rintf(b0) &&
            fabsf(b1) <= 127.f && b1 == rintf(b1)) { vb++; continue; }
        v8++;                                                            // packed int8 bytes
    }
    atomicAdd(&votes[0], v8); atomicAdd(&votes[1], v32);
    atomicAdd(&votes[2], vf); atomicAdd(&votes[3], vb);
    __syncthreads();
    if (threadIdx.x == 0) {
        int m = 0;
        for (int j = 1; j < 4; j++) if (votes[j] > votes[m]) m = j;
        g_mode = m;
    }
}

// ---------------- 0b. classify scale vs bias within each ambiguous pair ----------------
__global__ void classify_sb(const float* __restrict__ gua, const float* __restrict__ dna) {
    int lane = threadIdx.x;
    float a = gua[lane], b = dna[lane];
    unsigned m1 = __ballot_sync(0xffffffffu, a > 0.f && a < 1e-2f);  // scales ~3e-4, bias 0.02*N(0,1)
    unsigned m2 = __ballot_sync(0xffffffffu, b > 0.f && b < 1e-2f);
    if (lane == 0) {
        g_gu_swap = (m1 == 0xffffffffu) ? 0 : 1;
        g_dn_swap = (m2 == 0xffffffffu) ? 0 : 1;
    }
}

// ---------------- 0c. repack widened weights to packed int8 (no-op for mode 0) ----------------
__global__ void repack_w(const void* __restrict__ src, int8_t* __restrict__ dst, size_t n4) {
    int mode = g_mode;
    if (mode == 0) return;
    size_t stride = (size_t)gridDim.x * blockDim.x;
    for (size_t i = (size_t)blockIdx.x * blockDim.x + threadIdx.x; i < n4; i += stride) {
        int packed;
        if (mode == 1) {
            int4 v = ((const int4*)src)[i];
            packed = (v.x & 0xFF) | ((v.y & 0xFF) << 8) | ((v.z & 0xFF) << 16) | (v.w << 24);
        } else if (mode == 2) {
            float4 v = ((const float4*)src)[i];
            int a = __float2int_rn(v.x), b = __float2int_rn(v.y);
            int c = __float2int_rn(v.z), d = __float2int_rn(v.w);
            packed = (a & 0xFF) | ((b & 0xFF) << 8) | ((c & 0xFF) << 16) | (d << 24);
        } else {
            uint2 v = ((const uint2*)src)[i];
            int a = __float2int_rn(__uint_as_float((v.x & 0xFFFFu) << 16));
            int b = __float2int_rn(__uint_as_float(v.x & 0xFFFF0000u));
            int c = __float2int_rn(__uint_as_float((v.y & 0xFFFFu) << 16));
            int d = __float2int_rn(__uint_as_float(v.y & 0xFFFF0000u));
            packed = (a & 0xFF) | ((b & 0xFF) << 8) | ((c & 0xFF) << 16) | (d << 24);
        }
        ((int*)dst)[i] = packed;
    }
}

// ---------------- 1. routing: softmax + top-4 + renorm + capacity positions ----------------
__global__ void routing_kernel(const float* __restrict__ logits) {
    int tid = threadIdx.x;
    if (tid < NT) {
        float v[NE];
#pragma unroll
        for (int j = 0; j < NE; j++) v[j] = logits[tid * NE + j];
        int ids[NK]; float vals[NK];
#pragma unroll
        for (int k = 0; k < NK; k++) {
            int bi = 0; float bv = v[0];
#pragma unroll
            for (int j = 1; j < NE; j++)
                if (v[j] > bv) { bv = v[j]; bi = j; }
            ids[k] = bi; vals[k] = bv; v[bi] = -3.4e38f;
        }
        float m = vals[0], s = 0.f, w[NK];
#pragma unroll
        for (int k = 0; k < NK; k++) { w[k] = expf(vals[k] - m); s += w[k]; }
#pragma unroll
        for (int k = 0; k < NK; k++) {
            g_topk_w[tid * NK + k]  = w[k] / s;
            g_topk_ids[tid * NK + k] = ids[k];
        }
    }
    __syncthreads();
    int wp = tid >> 5, lane = tid & 31;
    if (wp < NE) {
        int cnt = 0;
        for (int base = 0; base < NT * NK; base += 32) {
            int fe = g_topk_ids[base + lane];
            unsigned msk = __ballot_sync(0xffffffffu, fe == wp);
            if (fe == wp) {
                int p = cnt + __popc(msk & ((1u << lane) - 1u));
                g_pos[base + lane] = p;
                if (p < NCAP) {
                    g_row_tok[wp * NCAP + p]  = (base + lane) >> 2;
                    g_row_flat[wp * NCAP + p] = base + lane;
                }
            }
            cnt += __popc(msk);
        }
        if (lane == 0) g_count[wp] = cnt;
    }
}

// ---------------- 2. per-token dynamic int8 quant ----------------
__global__ void quant_x(const float* __restrict__ x) {
    int t = blockIdx.x, tid = threadIdx.x;
    __shared__ float red[256];
    const float* row = x + (size_t)t * NH;
    float mx = 0.f;
    for (int i = tid; i < NH; i += 256) mx = fmaxf(mx, fabsf(row[i]));
    red[tid] = mx; __syncthreads();
    for (int s = 128; s > 0; s >>= 1) { if (tid < s) red[tid] = fmaxf(red[tid], red[tid + s]); __syncthreads(); }
    float sc = red[0] / 127.0f;
    if (tid == 0) g_xscale[t] = sc;
    float sd = (sc > 0.f) ? sc : 1.0f;
    for (int i = tid; i < NH; i += 256) {
        float q = rintf(row[i] / sd);
        q = fminf(fmaxf(q, -127.f), 127.f);
        g_qx[(size_t)t * NH + i] = (int8_t)q;
    }
}

// ---------------- grouped int8 GEMM (dp4a), BM=32 BN=128 BK=64, 256 threads ----------------
template <int NC, int EPI>
__global__ __launch_bounds__(256) void gemm_i8(const void* __restrict__ Worig,
                                               const int8_t* __restrict__ Wpack,
                                               const float* __restrict__ sb_a,
                                               const float* __restrict__ sb_b) {
    const int e  = blockIdx.y >> 3;
    const int m0 = (blockIdx.y & 7) * 32;
    const int cnt = g_count[e];
    if (m0 >= cnt) return;
    const int n0 = blockIdx.x * 128;

    const int8_t* wb = (g_mode == 0) ? (const int8_t*)Worig : Wpack;
    const int swap = (EPI == 1) ? g_gu_swap : g_dn_swap;
    const float* wsc = swap ? sb_b : sb_a;
    const float* wbi = swap ? sb_a : sb_b;

    __shared__ int as[16][36];
    __shared__ int bs[16][132];

    const int tid = threadIdx.x;
    const int tx = tid & 15, ty = tid >> 4;

    const int* arow[2]; int avalid[2];
#pragma unroll
    for (int r = 0; r < 2; r++) {
        int m = (tid + r * 256) >> 4;
        bool val = (m0 + m) < cnt;
        avalid[r] = val;
        if (EPI == 1) {
            int tok = val ? g_row_tok[e * NCAP + m0 + m] : 0;
            arow[r] = (const int*)(g_qx + (size_t)tok * NH);
        } else {
            arow[r] = (const int*)(g_q2 + (size_t)(e * NCAP + m0 + m) * NI);
        }
    }
    const int8_t* bp = wb + (size_t)e * 2048 * NC;

    int acc[2][8];
#pragma unroll
    for (int i = 0; i < 2; i++)
#pragma unroll
        for (int j = 0; j < 8; j++) acc[i][j] = 0;

    for (int kc = 0; kc < 32; kc++) {
#pragma unroll
        for (int r = 0; r < 2; r++) {
            int idx = tid + r * 256;
            int kk = idx & 15, m = idx >> 4;
            as[kk][m] = avalid[r] ? arow[r][kc * 16 + kk] : 0;
        }
#pragma unroll
        for (int r = 0; r < 2; r++) {
            int u = tid + r * 256;
            int kq = u >> 5;
            int n4 = (u & 31) * 4;
            const int8_t* src = bp + (size_t)(kc * 64 + kq * 4) * NC + n0 + n4;
            int r0 = *(const int*)(src);
            int r1 = *(const int*)(src + NC);
            int r2 = *(const int*)(src + 2 * NC);
            int r3 = *(const int*)(src + 3 * NC);
            int t0 = __byte_perm(r0, r1, 0x5140);
            int t1 = __byte_perm(r0, r1, 0x7362);
            int t2 = __byte_perm(r2, r3, 0x5140);
            int t3 = __byte_perm(r2, r3, 0x7362);
            bs[kq][n4 + 0] = __byte_perm(t0, t2, 0x5410);
            bs[kq][n4 + 1] = __byte_perm(t0, t2, 0x7632);
            bs[kq][n4 + 2] = __byte_perm(t1, t3, 0x5410);
            bs[kq][n4 + 3] = __byte_perm(t1, t3, 0x7632);
        }
        __syncthreads();
#pragma unroll
        for (int kk = 0; kk < 16; kk++) {
            const int2 a  = *(const int2*)&as[kk][ty * 2];
            const int4 b0 = *(const int4*)&bs[kk][tx * 8];
            const int4 b1 = *(const int4*)&bs[kk][tx * 8 + 4];
            int bb[8] = {b0.x, b0.y, b0.z, b0.w, b1.x, b1.y, b1.z, b1.w};
#pragma unroll
            for (int j = 0; j < 8; j++) {
                acc[0][j] = __dp4a(a.x, bb[j], acc[0][j]);
                acc[1][j] = __dp4a(a.y, bb[j], acc[1][j]);
            }
        }
        __syncthreads();
    }

    if (EPI == 1) {
#pragma unroll
        for (int i = 0; i < 2; i++) {
            int m = m0 + ty * 2 + i;
            if (m >= cnt) continue;
            int row = e * NCAP + m;
            float xs = g_xscale[g_row_tok[row]];
            int cbase = n0 + tx * 8;
            float4 o; float* op = &o.x;
#pragma unroll
            for (int p = 0; p < 4; p++) {
                int ce = cbase + 2 * p;
                float ve = (float)acc[i][2 * p]     * xs * wsc[(size_t)e * NC + ce]     + wbi[(size_t)e * NC + ce];
                float vo = (float)acc[i][2 * p + 1] * xs * wsc[(size_t)e * NC + ce + 1] + wbi[(size_t)e * NC + ce + 1];
                float glu = fminf(ve, 7.0f);
                float lin = fminf(fmaxf(vo, -7.0f), 7.0f);
                float sg  = 1.0f / (1.0f + expf(-1.702f * glu));
                op[p] = glu * sg * (lin + 1.0f);
            }
            *(float4*)&g_act[(size_t)row * NI + (cbase >> 1)] = o;
        }
    } else {
#pragma unroll
        for (int i = 0; i < 2; i++) {
            int m = m0 + ty * 2 + i;
            if (m >= cnt) continue;
            int row = e * NCAP + m;
            float s2 = g_s2[row];
            int flat = g_row_flat[row];
            int cb = n0 + tx * 8;
            float4 o0, o1; float* p0 = &o0.x; float* p1 = &o1.x;
#pragma unroll
            for (int j = 0; j < 4; j++) {
                p0[j] = (float)acc[i][j]     * s2 * wsc[(size_t)e * NC + cb + j]     + wbi[(size_t)e * NC + cb + j];
                p1[j] = (float)acc[i][4 + j] * s2 * wsc[(size_t)e * NC + cb + 4 + j] + wbi[(size_t)e * NC + cb + 4 + j];
            }
            float* dst = &g_dn[(size_t)flat * NH + cb];
            *(float4*)dst = o0;
            *(float4*)(dst + 4) = o1;
        }
    }
}

// ---------------- 4. requant activations ----------------
__global__ void quant_act() {
    int b = blockIdx.x;
    int e = b >> 8, m = b & 255;
    if (m >= g_count[e]) return;
    int tid = threadIdx.x;
    __shared__ float red[256];
    const float* row = &g_act[(size_t)b * NI];
    float mx = 0.f;
    for (int i = tid; i < NI; i += 256) mx = fmaxf(mx, fabsf(row[i]));
    red[tid] = mx; __syncthreads();
    for (int s = 128; s > 0; s >>= 1) { if (tid < s) red[tid] = fmaxf(red[tid], red[tid + s]); __syncthreads(); }
    float sc = red[0] / 127.0f;
    if (tid == 0) g_s2[b] = sc;
    float sd = (sc > 0.f) ? sc : 1.0f;
    for (int i = tid; i < NI; i += 256) {
        float q = rintf(row[i] / sd);
        q = fminf(fmaxf(q, -127.f), 127.f);
        g_q2[(size_t)b * NI + i] = (int8_t)q;
    }
}

// ---------------- 6. weighted gather-combine ----------------
__global__ void combine_kernel(float* __restrict__ out) {
    int t = blockIdx.x, tid = threadIdx.x;
    float w[NK]; int ps[NK];
#pragma unroll
    for (int k = 0; k < NK; k++) { w[k] = g_topk_w[t * NK + k]; ps[k] = g_pos[t * NK + k]; }
    for (int i = tid * 4; i < NH; i += 256 * 4) {
        float4 a = {0.f, 0.f, 0.f, 0.f};
#pragma unroll
        for (int k = 0; k < NK; k++) {
            if (ps[k] < NCAP) {
                float4 d = *(const float4*)&g_dn[(size_t)(t * NK + k) * NH + i];
                a.x += w[k] * d.x; a.y += w[k] * d.y;
                a.z += w[k] * d.z; a.w += w[k] * d.w;
            }
        }
        *(float4*)&out[(size_t)t * NH + i] = a;
    }
}

// ---------------- launch: identify inputs by element count, then run pipeline ----------------
extern "C" void kernel_launch(void* const* d_in, const int* in_sizes, int n_in,
                              void* d_out, int out_size) {
    int i_hs = 0, i_rl = 1, i_gu = 2, i_gus = 3, i_gub = 4, i_dn = 5, i_dns = 6, i_dnb = 7;
    if (n_in == 8) {
        int a_gu = -1, b_gu = -1, a_dn = -1, b_dn = -1;
        int hs = -1, rl = -1, gu = -1, dn = -1;
        for (int i = 0; i < n_in; i++) {
            int s = in_sizes[i];
            if (s == NT * NH) hs = i;
            else if (s == NT * NE) rl = i;
            else if (s == NE * NH * 2) { if (a_dn < 0) a_dn = i; else b_dn = i; } // 131072? no:
            else if (s == NE * NH) { if (a_dn < 0) a_dn = i; else b_dn = i; }
        }
        // redo cleanly (avoid the mistaken branch above)
        a_gu = b_gu = a_dn = b_dn = hs = rl = gu = dn = -1;
        for (int i = 0; i < n_in; i++) {
            long long s = in_sizes[i];
            if (s == (long long)NT * NH) hs = i;                       // 1,048,576
            else if (s == (long long)NT * NE) rl = i;                  // 16,384
            else if (s == (long long)NE * NH * N1) gu = i;             // 268,435,456
            else if (s == (long long)NE * NI * NH) dn = i;             // 134,217,728
            else if (s == (long long)NE * N1) { if (a_gu < 0) a_gu = i; else b_gu = i; }  // 131,072
            else if (s == (long long)NE * NH) { if (a_dn < 0) a_dn = i; else b_dn = i; }  // 65,536
        }
        if (hs >= 0 && rl >= 0 && gu >= 0 && dn >= 0 &&
            a_gu >= 0 && b_gu >= 0 && a_dn >= 0 && b_dn >= 0) {
            i_hs = hs; i_rl = rl; i_gu = gu; i_dn = dn;
            i_gus = a_gu; i_gub = b_gu; i_dns = a_dn; i_dnb = b_dn;
        }
    }

    const float* hs    = (const float*)d_in[i_hs];
    const float* rl    = (const float*)d_in[i_rl];
    const void*  gup   = d_in[i_gu];
    const float* gup_a = (const float*)d_in[i_gus];   // scale candidate (classified on device)
    const float* gup_b = (const float*)d_in[i_gub];
    const void*  dnw   = d_in[i_dn];
    const float* dn_a  = (const float*)d_in[i_dns];
    const float* dn_b  = (const float*)d_in[i_dnb];
    float* out = (float*)d_out;

    int8_t* wp1; int8_t* wp2;
    cudaGetSymbolAddress((void**)&wp1, g_wp1);
    cudaGetSymbolAddress((void**)&wp2, g_wp2);

    detect_dtype<<<1, 256>>>(gup);
    classify_sb<<<1, 32>>>(gup_a, dn_a);
    repack_w<<<16384, 256>>>(gup, wp1, (size_t)NE * NH * N1 / 4);
    repack_w<<<8192, 256>>>(dnw, wp2, (size_t)NE * NI * NH / 4);

    routing_kernel<<<1, 1024>>>(rl);
    quant_x<<<NT, 256>>>(hs);
    gemm_i8<N1, 1><<<dim3(32, NE * 8), 256>>>(gup, wp1, gup_a, gup_b);
    quant_act<<<NE * NCAP, 256>>>();
    gemm_i8<NH, 2><<<dim3(16, NE * 8), 256>>>(dnw, wp2, dn_a, dn_b);
    combine_kernel<<<NT, 256>>>(out);
}

// round 5
// speedup vs baseline: 1.5204x; 1.5204x over previous
#include <cuda_runtime.h>
#include <cuda_bf16.h>
#include <cstdint>
#include <cstddef>

#define NE   32
#define NK   4
#define NH   2048
#define NI   2048
#define NT   512
#define NCAP 256
#define N1   4096   // 2*I

// ---------------- scratch (static device globals; no runtime allocation) ----------------
__device__ int8_t g_qx[NT * NH];                       // 1 MB
__device__ float  g_xscale[NT];
__device__ int    g_topk_ids[NT * NK];
__device__ float  g_topk_w[NT * NK];
__device__ int    g_pos[NT * NK];
__device__ int    g_count[NE];
__device__ int    g_row_tok[NE * NCAP];
__device__ int    g_row_flat[NE * NCAP];
__device__ float  g_act[(size_t)NE * NCAP * NI];       // 64 MB
__device__ int8_t g_q2[(size_t)NE * NCAP * NI];        // 16 MB
__device__ float  g_s2[NE * NCAP];
__device__ float  g_dn[(size_t)NT * NK * NH];          // 16 MB

__device__ int    g_mode;                              // 0=int8 packed, 1=int32, 2=f32, 3=bf16
__device__ int    g_gu_swap;
__device__ int    g_dn_swap;

// ---------------- 0a. detect weight dtype encoding ----------------
__global__ void detect_dtype(const void* __restrict__ w) {
    __shared__ int votes[4];
    if (threadIdx.x < 4) votes[threadIdx.x] = 0;
    __syncthreads();
    const int* wi = (const int*)w;
    int v8 = 0, v32 = 0, vf = 0, vb = 0;
    for (int i = threadIdx.x; i < 8192; i += 256) {
        int v = wi[i];
        if (v == 0) continue;
        if (v >= -127 && v <= 127) { v32++; continue; }
        float f = __int_as_float(v);
        if (fabsf(f) <= 127.f && f == rintf(f)) { vf++; continue; }
        float b0 = __uint_as_float(((unsigned)v & 0xFFFFu) << 16);
        float b1 = __uint_as_float(((unsigned)v) & 0xFFFF0000u);
        if (fabsf(b0) <= 127.f && b0 == rintf(b0) &&
            fabsf(b1) <= 127.f && b1 == rintf(b1)) { vb++; continue; }
        v8++;
    }
    atomicAdd(&votes[0], v8); atomicAdd(&votes[1], v32);
    atomicAdd(&votes[2], vf); atomicAdd(&votes[3], vb);
    __syncthreads();
    if (threadIdx.x == 0) {
        int m = 0;
        for (int j = 1; j < 4; j++) if (votes[j] > votes[m]) m = j;
        g_mode = m;
    }
}

// ---------------- 0b. classify scale vs bias within each ambiguous pair ----------------
__global__ void classify_sb(const float* __restrict__ gua, const float* __restrict__ dna) {
    int lane = threadIdx.x;
    float a = gua[lane], b = dna[lane];
    unsigned m1 = __ballot_sync(0xffffffffu, a > 0.f && a < 1e-2f);
    unsigned m2 = __ballot_sync(0xffffffffu, b > 0.f && b < 1e-2f);
    if (lane == 0) {
        g_gu_swap = (m1 == 0xffffffffu) ? 0 : 1;
        g_dn_swap = (m2 == 0xffffffffu) ? 0 : 1;
    }
}

// ---------------- 1. routing ----------------
__global__ void routing_kernel(const float* __restrict__ logits) {
    int tid = threadIdx.x;
    if (tid < NT) {
        float v[NE];
#pragma unroll
        for (int j = 0; j < NE; j++) v[j] = logits[tid * NE + j];
        int ids[NK]; float vals[NK];
#pragma unroll
        for (int k = 0; k < NK; k++) {
            int bi = 0; float bv = v[0];
#pragma unroll
            for (int j = 1; j < NE; j++)
                if (v[j] > bv) { bv = v[j]; bi = j; }
            ids[k] = bi; vals[k] = bv; v[bi] = -3.4e38f;
        }
        float m = vals[0], s = 0.f, w[NK];
#pragma unroll
        for (int k = 0; k < NK; k++) { w[k] = expf(vals[k] - m); s += w[k]; }
#pragma unroll
        for (int k = 0; k < NK; k++) {
            g_topk_w[tid * NK + k]  = w[k] / s;
            g_topk_ids[tid * NK + k] = ids[k];
        }
    }
    __syncthreads();
    int wp = tid >> 5, lane = tid & 31;
    if (wp < NE) {
        int cnt = 0;
        for (int base = 0; base < NT * NK; base += 32) {
            int fe = g_topk_ids[base + lane];
            unsigned msk = __ballot_sync(0xffffffffu, fe == wp);
            if (fe == wp) {
                int p = cnt + __popc(msk & ((1u << lane) - 1u));
                g_pos[base + lane] = p;
                if (p < NCAP) {
                    g_row_tok[wp * NCAP + p]  = (base + lane) >> 2;
                    g_row_flat[wp * NCAP + p] = base + lane;
                }
            }
            cnt += __popc(msk);
        }
        if (lane == 0) g_count[wp] = cnt;
    }
}

// ---------------- 2. per-token dynamic int8 quant ----------------
__global__ void quant_x(const float* __restrict__ x) {
    int t = blockIdx.x, tid = threadIdx.x;
    __shared__ float red[256];
    const float* row = x + (size_t)t * NH;
    float mx = 0.f;
    for (int i = tid; i < NH; i += 256) mx = fmaxf(mx, fabsf(row[i]));
    red[tid] = mx; __syncthreads();
    for (int s = 128; s > 0; s >>= 1) { if (tid < s) red[tid] = fmaxf(red[tid], red[tid + s]); __syncthreads(); }
    float sc = red[0] / 127.0f;
    if (tid == 0) g_xscale[t] = sc;
    float sd = (sc > 0.f) ? sc : 1.0f;
    for (int i = tid; i < NH; i += 256) {
        float q = rintf(row[i] / sd);
        q = fminf(fmaxf(q, -127.f), 127.f);
        g_qx[(size_t)t * NH + i] = (int8_t)q;
    }
}

// ---------------- tensor-core grouped int8 GEMM, BM=128 BN=128 BK=64 ----------------
#define MMA_S8(d, a0, a1, a2, a3, b0, b1)                                         \
    asm volatile("mma.sync.aligned.m16n8k32.row.col.s32.s8.s8.s32 "               \
                 "{%0,%1,%2,%3}, {%4,%5,%6,%7}, {%8,%9}, {%0,%1,%2,%3};"          \
                 : "+r"(d[0]), "+r"(d[1]), "+r"(d[2]), "+r"(d[3])                 \
                 : "r"(a0), "r"(a1), "r"(a2), "r"(a3), "r"(b0), "r"(b1))

template <int MODE>
__device__ __forceinline__ int4 ldraw_w(const void* W, size_t ei) {
    int4 v = {0, 0, 0, 0};
    if (MODE == 0)      v.x = *(const int*)((const int8_t*)W + ei);
    else if (MODE == 3) { uint2 u = *(const uint2*)((const __nv_bfloat16*)W + ei);
                          v.x = (int)u.x; v.y = (int)u.y; }
    else                v = *(const int4*)((const int*)W + ei);   // int32 or f32 widened
    return v;
}

template <int MODE>
__device__ __forceinline__ int pack_w(int4 v) {
    if (MODE == 0) return v.x;
    if (MODE == 1) {
        int t0 = __byte_perm(v.x, v.y, 0x0040);
        int t1 = __byte_perm(v.z, v.w, 0x0040);
        return __byte_perm(t0, t1, 0x5410);
    }
    if (MODE == 2) {
        float4 f = *(float4*)&v;
        int a = __float2int_rn(f.x) & 255, b = __float2int_rn(f.y) & 255;
        int c = __float2int_rn(f.z) & 255, d = __float2int_rn(f.w);
        return a | (b << 8) | (c << 16) | (d << 24);
    }
    unsigned ux = (unsigned)v.x, uy = (unsigned)v.y;
    int a = __float2int_rn(__uint_as_float((ux & 0xFFFFu) << 16)) & 255;
    int b = __float2int_rn(__uint_as_float(ux & 0xFFFF0000u)) & 255;
    int c = __float2int_rn(__uint_as_float((uy & 0xFFFFu) << 16)) & 255;
    int d = __float2int_rn(__uint_as_float(uy & 0xFFFF0000u));
    return a | (b << 8) | (c << 16) | (d << 24);
}

// EPI==1: A = gathered g_qx rows, epilogue dequant+bias+swiglu -> g_act
// EPI==2: A = g_q2 rows,          epilogue dequant+bias -> g_dn[flat]
template <int NC, int EPI, int MODE>
__global__ __launch_bounds__(256, 1) void gemm_tc(const void* __restrict__ W,
                                                  const float* __restrict__ sb_a,
                                                  const float* __restrict__ sb_b) {
    if (g_mode != MODE) return;
    const int e  = blockIdx.y >> 1;
    const int m0 = (blockIdx.y & 1) * 128;
    const int cnt = g_count[e];
    if (m0 >= cnt) return;
    const int n0 = blockIdx.x * 128;

    const int swap = (EPI == 1) ? g_gu_swap : g_dn_swap;
    const float* wsc = swap ? sb_b : sb_a;
    const float* wbi = swap ? sb_a : sb_b;

    __shared__ int a_s[16][132];
    __shared__ int b_s[16][132];

    const int tid = threadIdx.x;
    const int lane = tid & 31, wid = tid >> 5;
    const int wm = (wid & 3) * 32;             // warp m-offset (4 m-warps x 32)
    const int wn = (wid >> 2) * 64;            // warp n-offset (2 n-warps x 64)
    const int g  = lane >> 2, tg = lane & 3;

    // per-thread load-slot coordinates (2 slots each for A and B)
    const int8_t* arow[2]; int aq[2], am[2]; bool avalid[2];
    int bkq[2], bn4[2];
#pragma unroll
    for (int i = 0; i < 2; i++) {
        int idx = tid + i * 256;
        am[i] = idx >> 2; aq[i] = idx & 3;
        int m = m0 + am[i];
        bool val = m < cnt;
        avalid[i] = val;
        if (EPI == 1) {
            int tok = val ? g_row_tok[e * NCAP + m] : 0;
            arow[i] = g_qx + (size_t)tok * NH;
        } else {
            arow[i] = g_q2 + (size_t)(e * NCAP + (val ? m : 0)) * NI;
        }
        bkq[i] = idx >> 5; bn4[i] = (idx & 31) * 4;
    }
    const size_t ebase = (size_t)e * 2048 * NC;

    int acc[2][8][4];
#pragma unroll
    for (int i = 0; i < 2; i++)
#pragma unroll
        for (int j = 0; j < 8; j++)
#pragma unroll
            for (int q = 0; q < 4; q++) acc[i][j][q] = 0;

    int4 ar[2];       // raw A prefetch
    int4 br[2][4];    // raw B prefetch (4 k-rows per 4x4 block)

    // ---- prefetch tile 0 ----
#pragma unroll
    for (int i = 0; i < 2; i++) {
        ar[i] = avalid[i] ? *(const int4*)(arow[i] + aq[i] * 16) : make_int4(0, 0, 0, 0);
#pragma unroll
        for (int j = 0; j < 4; j++)
            br[i][j] = ldraw_w<MODE>(W, ebase + (size_t)(bkq[i] * 4 + j) * NC + n0 + bn4[i]);
    }

    for (int kc = 0; kc < 32; kc++) {
        __syncthreads();
        // ---- store prefetched tile to smem ----
#pragma unroll
        for (int i = 0; i < 2; i++) {
            a_s[aq[i] * 4 + 0][am[i]] = ar[i].x;
            a_s[aq[i] * 4 + 1][am[i]] = ar[i].y;
            a_s[aq[i] * 4 + 2][am[i]] = ar[i].z;
            a_s[aq[i] * 4 + 3][am[i]] = ar[i].w;
            int r0 = pack_w<MODE>(br[i][0]);
            int r1 = pack_w<MODE>(br[i][1]);
            int r2 = pack_w<MODE>(br[i][2]);
            int r3 = pack_w<MODE>(br[i][3]);
            int t0 = __byte_perm(r0, r1, 0x5140);
            int t1 = __byte_perm(r0, r1, 0x7362);
            int t2 = __byte_perm(r2, r3, 0x5140);
            int t3 = __byte_perm(r2, r3, 0x7362);
            *(int4*)&b_s[bkq[i]][bn4[i]] = make_int4(__byte_perm(t0, t2, 0x5410),
                                                     __byte_perm(t0, t2, 0x7632),
                                                     __byte_perm(t1, t3, 0x5410),
                                                     __byte_perm(t1, t3, 0x7632));
        }
        __syncthreads();
        // ---- prefetch next tile (latency overlapped by mma below) ----
        if (kc < 31) {
            int ko = (kc + 1) * 64;
#pragma unroll
            for (int i = 0; i < 2; i++) {
                ar[i] = avalid[i] ? *(const int4*)(arow[i] + ko + aq[i] * 16) : make_int4(0, 0, 0, 0);
#pragma unroll
                for (int j = 0; j < 4; j++)
                    br[i][j] = ldraw_w<MODE>(W, ebase + (size_t)(ko + bkq[i] * 4 + j) * NC + n0 + bn4[i]);
            }
        }
        // ---- compute: 2 k-steps of m16n8k32 ----
#pragma unroll
        for (int ks = 0; ks < 2; ks++) {
            const int kb = ks * 8;
            int bf[8][2];
#pragma unroll
            for (int na = 0; na < 8; na++) {
                bf[na][0] = b_s[kb + tg][wn + na * 8 + g];
                bf[na][1] = b_s[kb + 4 + tg][wn + na * 8 + g];
            }
#pragma unroll
            for (int ma = 0; ma < 2; ma++) {
                int a0 = a_s[kb + tg][wm + ma * 16 + g];
                int a1 = a_s[kb + tg][wm + ma * 16 + g + 8];
                int a2 = a_s[kb + 4 + tg][wm + ma * 16 + g];
                int a3 = a_s[kb + 4 + tg][wm + ma * 16 + g + 8];
#pragma unroll
                for (int na = 0; na < 8; na++)
                    MMA_S8(acc[ma][na], a0, a1, a2, a3, bf[na][0], bf[na][1]);
            }
        }
    }

    // ---- epilogue ----
#pragma unroll
    for (int ma = 0; ma < 2; ma++) {
        int rbase = m0 + wm + ma * 16 + g;
#pragma unroll
        for (int half = 0; half < 2; half++) {
            int r = rbase + half * 8;
            if (r >= cnt) continue;
            int row = e * NCAP + r;
            if (EPI == 1) {
                float xs = g_xscale[g_row_tok[row]];
#pragma unroll
                for (int na = 0; na < 8; na++) {
                    int c = n0 + wn + na * 8 + 2 * tg;
                    float ve = (float)acc[ma][na][half * 2]     * xs * wsc[(size_t)e * NC + c]     + wbi[(size_t)e * NC + c];
                    float vo = (float)acc[ma][na][half * 2 + 1] * xs * wsc[(size_t)e * NC + c + 1] + wbi[(size_t)e * NC + c + 1];
                    float glu = fminf(ve, 7.0f);
                    float lin = fminf(fmaxf(vo, -7.0f), 7.0f);
                    float sg  = 1.0f / (1.0f + expf(-1.702f * glu));
                    g_act[(size_t)row * NI + (c >> 1)] = glu * sg * (lin + 1.0f);
                }
            } else {
                float s2 = g_s2[row];
                int flat = g_row_flat[row];
#pragma unroll
                for (int na = 0; na < 8; na++) {
                    int c = n0 + wn + na * 8 + 2 * tg;
                    float o0 = (float)acc[ma][na][half * 2]     * s2 * wsc[(size_t)e * NC + c]     + wbi[(size_t)e * NC + c];
                    float o1 = (float)acc[ma][na][half * 2 + 1] * s2 * wsc[(size_t)e * NC + c + 1] + wbi[(size_t)e * NC + c + 1];
                    *(float2*)&g_dn[(size_t)flat * NH + c] = make_float2(o0, o1);
                }
            }
        }
    }
}

// ---------------- 4. requant activations ----------------
__global__ void quant_act() {
    int b = blockIdx.x;
    int e = b >> 8, m = b & 255;
    if (m >= g_count[e]) return;
    int tid = threadIdx.x;
    __shared__ float red[256];
    const float* row = &g_act[(size_t)b * NI];
    float mx = 0.f;
    for (int i = tid; i < NI; i += 256) mx = fmaxf(mx, fabsf(row[i]));
    red[tid] = mx; __syncthreads();
    for (int s = 128; s > 0; s >>= 1) { if (tid < s) red[tid] = fmaxf(red[tid], red[tid + s]); __syncthreads(); }
    float sc = red[0] / 127.0f;
    if (tid == 0) g_s2[b] = sc;
    float sd = (sc > 0.f) ? sc : 1.0f;
    for (int i = tid; i < NI; i += 256) {
        float q = rintf(row[i] / sd);
        q = fminf(fmaxf(q, -127.f), 127.f);
        g_q2[(size_t)b * NI + i] = (int8_t)q;
    }
}

// ---------------- 6. weighted gather-combine ----------------
__global__ void combine_kernel(float* __restrict__ out) {
    int t = blockIdx.x, tid = threadIdx.x;
    float w[NK]; int ps[NK];
#pragma unroll
    for (int k = 0; k < NK; k++) { w[k] = g_topk_w[t * NK + k]; ps[k] = g_pos[t * NK + k]; }
    for (int i = tid * 4; i < NH; i += 256 * 4) {
        float4 a = {0.f, 0.f, 0.f, 0.f};
#pragma unroll
        for (int k = 0; k < NK; k++) {
            if (ps[k] < NCAP) {
                float4 d = *(const float4*)&g_dn[(size_t)(t * NK + k) * NH + i];
                a.x += w[k] * d.x; a.y += w[k] * d.y;
                a.z += w[k] * d.z; a.w += w[k] * d.w;
            }
        }
        *(float4*)&out[(size_t)t * NH + i] = a;
    }
}

// ---------------- launch ----------------
extern "C" void kernel_launch(void* const* d_in, const int* in_sizes, int n_in,
                              void* d_out, int out_size) {
    int i_hs = 0, i_rl = 1, i_gu = 2, i_gus = 3, i_gub = 4, i_dn = 5, i_dns = 6, i_dnb = 7;
    if (n_in == 8) {
        int a_gu = -1, b_gu = -1, a_dn = -1, b_dn = -1;
        int hs = -1, rl = -1, gu = -1, dn = -1;
        for (int i = 0; i < n_in; i++) {
            long long s = in_sizes[i];
            if (s == (long long)NT * NH) hs = i;
            else if (s == (long long)NT * NE) rl = i;
            else if (s == (long long)NE * NH * N1) gu = i;
            else if (s == (long long)NE * NI * NH) dn = i;
            else if (s == (long long)NE * N1) { if (a_gu < 0) a_gu = i; else b_gu = i; }
            else if (s == (long long)NE * NH) { if (a_dn < 0) a_dn = i; else b_dn = i; }
        }
        if (hs >= 0 && rl >= 0 && gu >= 0 && dn >= 0 &&
            a_gu >= 0 && b_gu >= 0 && a_dn >= 0 && b_dn >= 0) {
            i_hs = hs; i_rl = rl; i_gu = gu; i_dn = dn;
            i_gus = a_gu; i_gub = b_gu; i_dns = a_dn; i_dnb = b_dn;
        }
    }

    const float* hs    = (const float*)d_in[i_hs];
    const float* rl    = (const float*)d_in[i_rl];
    const void*  gup   = d_in[i_gu];
    const float* gup_a = (const float*)d_in[i_gus];
    const float* gup_b = (const float*)d_in[i_gub];
    const void*  dnw   = d_in[i_dn];
    const float* dn_a  = (const float*)d_in[i_dns];
    const float* dn_b  = (const float*)d_in[i_dnb];
    float* out = (float*)d_out;

    detect_dtype<<<1, 256>>>(gup);
    classify_sb<<<1, 32>>>(gup_a, dn_a);
    routing_kernel<<<1, 1024>>>(rl);
    quant_x<<<NT, 256>>>(hs);

    dim3 g1(N1 / 128, NE * 2), g2(NH / 128, NE * 2);
    gemm_tc<N1, 1, 0><<<g1, 256>>>(gup, gup_a, gup_b);
    gemm_tc<N1, 1, 1><<<g1, 256>>>(gup, gup_a, gup_b);
    gemm_tc<N1, 1, 2><<<g1, 256>>>(gup, gup_a, gup_b);
    gemm_tc<N1, 1, 3><<<g1, 256>>>(gup, gup_a, gup_b);

    quant_act<<<NE * NCAP, 256>>>();

    gemm_tc<NH, 2, 0><<<g2, 256>>>(dnw, dn_a, dn_b);
    gemm_tc<NH, 2, 1><<<g2, 256>>>(dnw, dn_a, dn_b);
    gemm_tc<NH, 2, 2><<<g2, 256>>>(dnw, dn_a, dn_b);
    gemm_tc<NH, 2, 3><<<g2, 256>>>(dnw, dn_a, dn_b);

    combine_kernel<<<NT, 256>>>(out);
}